// round 2
// baseline (speedup 1.0000x reference)
#include <cuda_runtime.h>
#include <cuda_bf16.h>
#include <math.h>

// ---------------------------------------------------------------------------
// WideDeep: gather/mean embeddings -> concat [8192,748] -> 3-layer MLP -> GEMV
// Round 1: correct fp32 baseline. GEMMs are classic SGEMM (128x128x8 tiles,
// 8x8 per-thread microtile). Tensor-core (tcgen05 bf16) port planned next.
// ---------------------------------------------------------------------------

#define B_SZ   8192
#define L_TOK  32
#define L_MH   20
#define EMB    64
#define TOK_D  300
#define K1     748
#define N1     1024
#define N2     512
#define N3     256

// Scratch (allocation-free rule: __device__ globals)
__device__ float g_emb[B_SZ * K1];     // 24.5 MB
__device__ float g_h1 [B_SZ * N1];     // 32 MB
__device__ float g_h2 [B_SZ * N2];     // 16 MB
__device__ float g_h3 [B_SZ * N3];     // 8 MB
__device__ float g_wide[B_SZ];

// ---------------------------------------------------------------------------
// Kernel 1: embedding gather + mean + concat + wide tower
// One block per batch row, 256 threads.
// ---------------------------------------------------------------------------
__global__ __launch_bounds__(256) void embed_kernel(
    const int* __restrict__ tok, const int* __restrict__ m1,
    const int* __restrict__ m2,  const int* __restrict__ m3,
    const int* __restrict__ o1,  const int* __restrict__ o2,
    const int* __restrict__ o3,  const int* __restrict__ o4,
    const float* __restrict__ we,
    const float* __restrict__ em1, const float* __restrict__ em2,
    const float* __restrict__ em3,
    const float* __restrict__ eo1, const float* __restrict__ eo2,
    const float* __restrict__ eo3, const float* __restrict__ eo4,
    const float* __restrict__ wm1, const float* __restrict__ wm2,
    const float* __restrict__ wm3,
    const float* __restrict__ wo1, const float* __restrict__ wo2,
    const float* __restrict__ wo3, const float* __restrict__ wo4)
{
    const int b   = blockIdx.x;
    const int tid = threadIdx.x;

    __shared__ int s_tok[L_TOK];
    __shared__ int s_m1[L_MH], s_m2[L_MH], s_m3[L_MH];
    __shared__ int s_oh[4];

    if (tid < 32)       s_tok[tid]      = tok[b * L_TOK + tid];
    else if (tid < 52)  s_m1[tid - 32]  = m1[b * L_MH + tid - 32];
    else if (tid < 72)  s_m2[tid - 52]  = m2[b * L_MH + tid - 52];
    else if (tid < 92)  s_m3[tid - 72]  = m3[b * L_MH + tid - 72];
    else if (tid == 92) s_oh[0] = o1[b];
    else if (tid == 93) s_oh[1] = o2[b];
    else if (tid == 94) s_oh[2] = o3[b];
    else if (tid == 95) s_oh[3] = o4[b];
    __syncthreads();

    float* eb = g_emb + (size_t)b * K1;

    // token embedding-bag mean: dims [0, 300)
    for (int d = tid; d < TOK_D; d += 256) {
        float s = 0.f;
        #pragma unroll 8
        for (int j = 0; j < L_TOK; j++)
            s += we[(size_t)s_tok[j] * TOK_D + d];
        eb[d] = s * (1.0f / 32.0f);
    }

    // mh1/mh2/mh3 mean + oh1 : dims [300, 556)
    {
        const int f = tid >> 6, d = tid & 63;
        if (f == 0) {
            float s = 0.f;
            #pragma unroll
            for (int j = 0; j < L_MH; j++) s += em1[s_m1[j] * EMB + d];
            eb[300 + d] = s * 0.05f;
        } else if (f == 1) {
            float s = 0.f;
            #pragma unroll
            for (int j = 0; j < L_MH; j++) s += em2[s_m2[j] * EMB + d];
            eb[364 + d] = s * 0.05f;
        } else if (f == 2) {
            float s = 0.f;
            #pragma unroll
            for (int j = 0; j < L_MH; j++) s += em3[s_m3[j] * EMB + d];
            eb[428 + d] = s * 0.05f;
        } else {
            eb[492 + d] = eo1[s_oh[0] * EMB + d];
        }
    }

    // oh2/oh3/oh4 : dims [556, 748) + wide tower
    {
        const int f = tid >> 6, d = tid & 63;
        if (f == 0)      eb[556 + d] = eo2[s_oh[1] * EMB + d];
        else if (f == 1) eb[620 + d] = eo3[s_oh[2] * EMB + d];
        else if (f == 2) eb[684 + d] = eo4[s_oh[3] * EMB + d];
        else if (d == 0) {
            float s = 0.f;
            #pragma unroll
            for (int j = 0; j < L_MH; j++)
                s += wm1[s_m1[j]] + wm2[s_m2[j]] + wm3[s_m3[j]];
            s += wo1[s_oh[0]] + wo2[s_oh[1]] + wo3[s_oh[2]] + wo4[s_oh[3]];
            g_wide[b] = s;
        }
    }
}

// ---------------------------------------------------------------------------
// Kernel 2: SGEMM  C[M,N] = act(A[M,K] @ W[K,N] + bias)
// 128x128 block tile, BK=8, 256 threads, 8x8 microtile. M,N multiples of 128;
// K only needs K % 4 == 0 (748, 1024, 512 all qualify).
// ---------------------------------------------------------------------------
template <bool RELU>
__global__ __launch_bounds__(256, 2) void sgemm_kernel(
    const float* __restrict__ A, const float* __restrict__ W,
    const float* __restrict__ bias, float* __restrict__ C,
    int M, int N, int K)
{
    const int BM = 128, BN = 128, BK = 8;
    __shared__ float As[BK][BM];
    __shared__ float Bs[BK][BN];

    const int tid = threadIdx.x;
    const int bm  = blockIdx.y * BM;
    const int bn  = blockIdx.x * BN;
    const int tx  = tid & 15;          // 0..15 -> N
    const int ty  = tid >> 4;          // 0..15 -> M

    // global load assignments
    const int a_row = tid >> 1;        // 0..127
    const int a_col = (tid & 1) * 4;   // 0 or 4
    const int b_row = tid >> 5;        // 0..7
    const int b_col = (tid & 31) * 4;  // 0..124

    float acc[8][8];
    #pragma unroll
    for (int i = 0; i < 8; i++)
        #pragma unroll
        for (int j = 0; j < 8; j++) acc[i][j] = 0.f;

    for (int k0 = 0; k0 < K; k0 += BK) {
        // A tile -> transposed into As[k][m]
        float4 av = make_float4(0.f, 0.f, 0.f, 0.f);
        if (k0 + a_col < K)   // K%4==0 so all 4 lanes valid together
            av = *(const float4*)(A + (size_t)(bm + a_row) * K + k0 + a_col);
        As[a_col + 0][a_row] = av.x;
        As[a_col + 1][a_row] = av.y;
        As[a_col + 2][a_row] = av.z;
        As[a_col + 3][a_row] = av.w;

        // W tile -> Bs[k][n]
        float4 bv = make_float4(0.f, 0.f, 0.f, 0.f);
        if (k0 + b_row < K)
            bv = *(const float4*)(W + (size_t)(k0 + b_row) * N + bn + b_col);
        *(float4*)&Bs[b_row][b_col] = bv;

        __syncthreads();

        #pragma unroll
        for (int kk = 0; kk < BK; kk++) {
            float a[8], bb[8];
            *(float4*)(a)     = *(const float4*)&As[kk][ty * 8];
            *(float4*)(a + 4) = *(const float4*)&As[kk][ty * 8 + 4];
            *(float4*)(bb)    = *(const float4*)&Bs[kk][tx * 8];
            *(float4*)(bb + 4)= *(const float4*)&Bs[kk][tx * 8 + 4];
            #pragma unroll
            for (int i = 0; i < 8; i++)
                #pragma unroll
                for (int j = 0; j < 8; j++)
                    acc[i][j] += a[i] * bb[j];
        }
        __syncthreads();
    }

    // epilogue: bias + optional ReLU, vectorized store
    float4 bv0 = *(const float4*)(bias + bn + tx * 8);
    float4 bv1 = *(const float4*)(bias + bn + tx * 8 + 4);
    const float bvals[8] = {bv0.x, bv0.y, bv0.z, bv0.w, bv1.x, bv1.y, bv1.z, bv1.w};

    #pragma unroll
    for (int i = 0; i < 8; i++) {
        const int r = bm + ty * 8 + i;
        float o[8];
        #pragma unroll
        for (int j = 0; j < 8; j++) {
            float v = acc[i][j] + bvals[j];
            o[j] = RELU ? fmaxf(v, 0.f) : v;
        }
        float* cp = C + (size_t)r * N + bn + tx * 8;
        *(float4*)(cp)     = *(float4*)(o);
        *(float4*)(cp + 4) = *(float4*)(o + 4);
    }
}

// ---------------------------------------------------------------------------
// Kernel 3: final GEMV + wide + sigmoid.  One warp per batch row.
// ---------------------------------------------------------------------------
__global__ __launch_bounds__(256) void final_kernel(
    const float* __restrict__ Wd, const float* __restrict__ bd,
    float* __restrict__ out)
{
    const int warp = threadIdx.x >> 5;
    const int lane = threadIdx.x & 31;
    const int b    = blockIdx.x * 8 + warp;

    const float* h = g_h3 + (size_t)b * N3;
    float s = 0.f;
    #pragma unroll
    for (int i = lane; i < N3; i += 32) s += h[i] * Wd[i];
    #pragma unroll
    for (int o = 16; o; o >>= 1) s += __shfl_xor_sync(0xFFFFFFFFu, s, o);

    if (lane == 0) {
        const float logit = s + bd[0] + g_wide[b];
        out[b] = 1.0f / (1.0f + expf(-logit));
    }
}

// ---------------------------------------------------------------------------
extern "C" void kernel_launch(void* const* d_in, const int* in_sizes, int n_in,
                              void* d_out, int out_size)
{
    (void)in_sizes; (void)n_in; (void)out_size;

    const int*   tok = (const int*)d_in[0];
    const int*   m1  = (const int*)d_in[1];
    const int*   m2  = (const int*)d_in[2];
    const int*   m3  = (const int*)d_in[3];
    const int*   o1  = (const int*)d_in[4];
    const int*   o2  = (const int*)d_in[5];
    const int*   o3  = (const int*)d_in[6];
    const int*   o4  = (const int*)d_in[7];
    const float* we  = (const float*)d_in[8];
    const float* em1 = (const float*)d_in[9];
    const float* em2 = (const float*)d_in[10];
    const float* em3 = (const float*)d_in[11];
    const float* eo1 = (const float*)d_in[12];
    const float* eo2 = (const float*)d_in[13];
    const float* eo3 = (const float*)d_in[14];
    const float* eo4 = (const float*)d_in[15];
    const float* wm1 = (const float*)d_in[16];
    const float* wm2 = (const float*)d_in[17];
    const float* wm3 = (const float*)d_in[18];
    const float* wo1 = (const float*)d_in[19];
    const float* wo2 = (const float*)d_in[20];
    const float* wo3 = (const float*)d_in[21];
    const float* wo4 = (const float*)d_in[22];
    const float* W1  = (const float*)d_in[23];
    const float* b1  = (const float*)d_in[24];
    const float* W2  = (const float*)d_in[25];
    const float* b2  = (const float*)d_in[26];
    const float* W3  = (const float*)d_in[27];
    const float* b3  = (const float*)d_in[28];
    const float* Wd  = (const float*)d_in[29];
    const float* bd  = (const float*)d_in[30];
    float* out = (float*)d_out;

    float *p_emb, *p_h1, *p_h2, *p_h3;
    cudaGetSymbolAddress((void**)&p_emb, g_emb);
    cudaGetSymbolAddress((void**)&p_h1,  g_h1);
    cudaGetSymbolAddress((void**)&p_h2,  g_h2);
    cudaGetSymbolAddress((void**)&p_h3,  g_h3);

    embed_kernel<<<B_SZ, 256>>>(tok, m1, m2, m3, o1, o2, o3, o4,
                                we, em1, em2, em3, eo1, eo2, eo3, eo4,
                                wm1, wm2, wm3, wo1, wo2, wo3, wo4);

    sgemm_kernel<true><<<dim3(N1 / 128, B_SZ / 128), 256>>>(p_emb, W1, b1, p_h1, B_SZ, N1, K1);
    sgemm_kernel<true><<<dim3(N2 / 128, B_SZ / 128), 256>>>(p_h1,  W2, b2, p_h2, B_SZ, N2, N1);
    sgemm_kernel<true><<<dim3(N3 / 128, B_SZ / 128), 256>>>(p_h2,  W3, b3, p_h3, B_SZ, N3, N2);

    final_kernel<<<B_SZ / 8, 256>>>(Wd, bd, out);
}

// round 4
// speedup vs baseline: 4.2814x; 4.2814x over previous
#include <cuda_runtime.h>
#include <cuda_bf16.h>
#include <math.h>
#include <stdint.h>

// ---------------------------------------------------------------------------
// WideDeep round 3: tensor-core GEMMs via mma.sync (m16n8k16 bf16, sm_80+ ISA
// -- the harness targets compute_100 WITHOUT the 'a' suffix, so tcgen05 is
// unavailable). cp.async double-buffered smem, swizzled, 128x128x32 tiles.
// ---------------------------------------------------------------------------

#define B_SZ   8192
#define L_TOK  32
#define L_MH   20
#define EMB    64
#define TOK_D  300
#define K1     748
#define K1P    768      // padded to multiple of 32
#define N1     1024
#define N2     512
#define N3     256

// Scratch (__device__ globals; allocation-free rule)
__device__ __nv_bfloat16 g_embB[B_SZ * K1P];
__device__ __nv_bfloat16 g_h1b [B_SZ * N1];
__device__ __nv_bfloat16 g_h2b [B_SZ * N2];
__device__ __nv_bfloat16 g_h3b [B_SZ * N3];
__device__ __nv_bfloat16 g_Wt1 [N1 * K1P];   // [N, Kpad] bf16 (W transposed)
__device__ __nv_bfloat16 g_Wt2 [N2 * N1];
__device__ __nv_bfloat16 g_Wt3 [N3 * N2];
__device__ float g_wide[B_SZ];

__device__ __forceinline__ uint32_t smem_u32(const void* p) {
    uint32_t a;
    asm("{ .reg .u64 t; cvta.to.shared.u64 t, %1; cvt.u32.u64 %0, t; }"
        : "=r"(a) : "l"(p));
    return a;
}

// ---------------------------------------------------------------------------
// Kernel 1: embedding gather + mean + concat (bf16, K-padded) + wide tower
// ---------------------------------------------------------------------------
__global__ __launch_bounds__(256) void embed_kernel(
    const int* __restrict__ tok, const int* __restrict__ m1,
    const int* __restrict__ m2,  const int* __restrict__ m3,
    const int* __restrict__ o1,  const int* __restrict__ o2,
    const int* __restrict__ o3,  const int* __restrict__ o4,
    const float* __restrict__ we,
    const float* __restrict__ em1, const float* __restrict__ em2,
    const float* __restrict__ em3,
    const float* __restrict__ eo1, const float* __restrict__ eo2,
    const float* __restrict__ eo3, const float* __restrict__ eo4,
    const float* __restrict__ wm1, const float* __restrict__ wm2,
    const float* __restrict__ wm3,
    const float* __restrict__ wo1, const float* __restrict__ wo2,
    const float* __restrict__ wo3, const float* __restrict__ wo4)
{
    const int b   = blockIdx.x;
    const int tid = threadIdx.x;

    __shared__ int s_tok[L_TOK];
    __shared__ int s_m1[L_MH], s_m2[L_MH], s_m3[L_MH];
    __shared__ int s_oh[4];

    if (tid < 32)       s_tok[tid]      = tok[b * L_TOK + tid];
    else if (tid < 52)  s_m1[tid - 32]  = m1[b * L_MH + tid - 32];
    else if (tid < 72)  s_m2[tid - 52]  = m2[b * L_MH + tid - 52];
    else if (tid < 92)  s_m3[tid - 72]  = m3[b * L_MH + tid - 72];
    else if (tid == 92) s_oh[0] = o1[b];
    else if (tid == 93) s_oh[1] = o2[b];
    else if (tid == 94) s_oh[2] = o3[b];
    else if (tid == 95) s_oh[3] = o4[b];
    __syncthreads();

    __nv_bfloat16* eb = g_embB + (size_t)b * K1P;

    if (tid < K1P - K1) eb[K1 + tid] = __float2bfloat16(0.f);

    for (int d = tid; d < TOK_D; d += 256) {
        float s = 0.f;
        #pragma unroll 8
        for (int j = 0; j < L_TOK; j++)
            s += we[(size_t)s_tok[j] * TOK_D + d];
        eb[d] = __float2bfloat16(s * (1.0f / 32.0f));
    }

    {
        const int f = tid >> 6, d = tid & 63;
        if (f == 0) {
            float s = 0.f;
            #pragma unroll
            for (int j = 0; j < L_MH; j++) s += em1[s_m1[j] * EMB + d];
            eb[300 + d] = __float2bfloat16(s * 0.05f);
        } else if (f == 1) {
            float s = 0.f;
            #pragma unroll
            for (int j = 0; j < L_MH; j++) s += em2[s_m2[j] * EMB + d];
            eb[364 + d] = __float2bfloat16(s * 0.05f);
        } else if (f == 2) {
            float s = 0.f;
            #pragma unroll
            for (int j = 0; j < L_MH; j++) s += em3[s_m3[j] * EMB + d];
            eb[428 + d] = __float2bfloat16(s * 0.05f);
        } else {
            eb[492 + d] = __float2bfloat16(eo1[s_oh[0] * EMB + d]);
        }
    }

    {
        const int f = tid >> 6, d = tid & 63;
        if (f == 0)      eb[556 + d] = __float2bfloat16(eo2[s_oh[1] * EMB + d]);
        else if (f == 1) eb[620 + d] = __float2bfloat16(eo3[s_oh[2] * EMB + d]);
        else if (f == 2) eb[684 + d] = __float2bfloat16(eo4[s_oh[3] * EMB + d]);
        else if (d == 0) {
            float s = 0.f;
            #pragma unroll
            for (int j = 0; j < L_MH; j++)
                s += wm1[s_m1[j]] + wm2[s_m2[j]] + wm3[s_m3[j]];
            s += wo1[s_oh[0]] + wo2[s_oh[1]] + wo3[s_oh[2]] + wo4[s_oh[3]];
            g_wide[b] = s;
        }
    }
}

// ---------------------------------------------------------------------------
// Prep: W[K,N] fp32 -> Wt[N,Kpad] bf16 (transpose + pad)
// ---------------------------------------------------------------------------
__global__ __launch_bounds__(256) void prep_wt_kernel(
    const float* __restrict__ W, __nv_bfloat16* __restrict__ Wt,
    int K, int N, int Kpad)
{
    int i = blockIdx.x * 256 + threadIdx.x;
    if (i >= N * Kpad) return;
    int n = i / Kpad, k = i - n * Kpad;
    Wt[i] = __float2bfloat16(k < K ? W[(size_t)k * N + n] : 0.f);
}

// ---------------------------------------------------------------------------
// Tensor-core GEMM: C[M,N] = relu(A[M,K] @ Wt[N,K]^T + bias) -> bf16
// A, Wt bf16 K-major. 128x128x32 CTA tile, 256 threads (2x4 warps, 64x32
// warp tile), mma.sync m16n8k16, cp.async double buffer, XOR-swizzled smem.
//
// SMEM layout per stage: A tile 128 rows x 32 cols bf16, row stride 64B,
// 16B chunk c of row r stored at chunk (c ^ ((r>>1)&3)). B tile identical.
// ---------------------------------------------------------------------------
__device__ __forceinline__ void mma16816(float c[4], const uint32_t a[4],
                                         const uint32_t b[2])
{
    asm volatile(
        "mma.sync.aligned.m16n8k16.row.col.f32.bf16.bf16.f32 "
        "{%0,%1,%2,%3}, {%4,%5,%6,%7}, {%8,%9}, {%0,%1,%2,%3};"
        : "+f"(c[0]), "+f"(c[1]), "+f"(c[2]), "+f"(c[3])
        : "r"(a[0]), "r"(a[1]), "r"(a[2]), "r"(a[3]), "r"(b[0]), "r"(b[1]));
}

__global__ __launch_bounds__(256, 2) void gemm_tc_kernel(
    const __nv_bfloat16* __restrict__ A, const __nv_bfloat16* __restrict__ Bt,
    const float* __restrict__ bias, __nv_bfloat16* __restrict__ C,
    int Nout, int K)
{
    __shared__ __align__(1024) char sm[2 * 16384];   // 2 stages x (A 8K + B 8K)

    const int tid  = threadIdx.x;
    const int lane = tid & 31, warp = tid >> 5;
    const int wm   = warp & 1;        // warp row   -> m offset wm*64
    const int wn   = warp >> 1;       // warp col   -> n offset wn*32
    const int gid  = lane >> 2;       // groupID (0..7)
    const int tig  = lane & 3;        // thread-in-group
    const int bm   = blockIdx.y * 128, bn = blockIdx.x * 128;

    // ---- cp.async assignments: 512 16B chunks per tile, 2 per thread ----
    int rowA[2], offA[2], gA[2], offB[2], gB[2];
    #pragma unroll
    for (int j = 0; j < 2; j++) {
        const int c  = tid + j * 256;
        const int r  = c >> 2, ch = c & 3;
        rowA[j] = r;
        offA[j] = r * 64 + ((ch ^ ((r >> 1) & 3)) << 4);
        gA[j]   = (bm + r) * K + ch * 8;       // element offset
        offB[j] = offA[j];
        gB[j]   = (bn + r) * K + ch * 8;
    }

    const int NIT = K >> 5;   // K / 32

    // ---- fragment load offsets (byte, within stage) ----
    // A frag reg r of mfrag mf at k-step s:
    //   row = wm*64 + mf*16 + gid + (r&1)*8 ; chunk = s*2 + (r>>1); +tig*4
    uint32_t aoff[4][4], boff[4][2];
    #pragma unroll
    for (int mf = 0; mf < 4; mf++)
        #pragma unroll
        for (int r = 0; r < 4; r++) {
            const int row = wm * 64 + mf * 16 + gid + (r & 1) * 8;
            const int ch  = (r >> 1);   // + s*2 added at use
            aoff[mf][r] = row * 64 + tig * 4 + (((row >> 1) & 3) << 4) /*xor key*/
                          + (ch << 30);  // stash ch in high bits? no -- keep simple
        }
    // The xor must be applied to (s*2 + ch), so precompute row part only.
    uint32_t arow64[4][4]; int achunk[4][4];
    #pragma unroll
    for (int mf = 0; mf < 4; mf++)
        #pragma unroll
        for (int r = 0; r < 4; r++) {
            const int row = wm * 64 + mf * 16 + gid + (r & 1) * 8;
            arow64[mf][r] = row * 64 + tig * 4;
            achunk[mf][r] = ((row >> 1) & 3);   // xor key
        }
    uint32_t brow64[4]; int bxor[4];
    #pragma unroll
    for (int nf = 0; nf < 4; nf++) {
        const int row = wn * 32 + nf * 8 + gid;
        brow64[nf] = row * 64 + tig * 4;
        bxor[nf]   = ((row >> 1) & 3);
    }
    (void)aoff; (void)boff;

    float acc[4][4][4];
    #pragma unroll
    for (int mf = 0; mf < 4; mf++)
        #pragma unroll
        for (int nf = 0; nf < 4; nf++)
            #pragma unroll
            for (int i = 0; i < 4; i++) acc[mf][nf][i] = 0.f;

    // ---- prefetch stage 0 ----
    {
        char* s = sm;
        #pragma unroll
        for (int j = 0; j < 2; j++) {
            uint32_t da = smem_u32(s + offA[j]);
            uint32_t db = smem_u32(s + 8192 + offB[j]);
            asm volatile("cp.async.cg.shared.global [%0], [%1], 16;"
                         :: "r"(da), "l"(A + gA[j]) : "memory");
            asm volatile("cp.async.cg.shared.global [%0], [%1], 16;"
                         :: "r"(db), "l"(Bt + gB[j]) : "memory");
        }
        asm volatile("cp.async.commit_group;" ::: "memory");
    }

    for (int it = 0; it < NIT; it++) {
        if (it + 1 < NIT) {
            char* s = sm + ((it + 1) & 1) * 16384;
            const int k0 = (it + 1) * 32;
            #pragma unroll
            for (int j = 0; j < 2; j++) {
                uint32_t da = smem_u32(s + offA[j]);
                uint32_t db = smem_u32(s + 8192 + offB[j]);
                asm volatile("cp.async.cg.shared.global [%0], [%1], 16;"
                             :: "r"(da), "l"(A + gA[j] + k0) : "memory");
                asm volatile("cp.async.cg.shared.global [%0], [%1], 16;"
                             :: "r"(db), "l"(Bt + gB[j] + k0) : "memory");
            }
            asm volatile("cp.async.commit_group;" ::: "memory");
            asm volatile("cp.async.wait_group 1;" ::: "memory");
        } else {
            asm volatile("cp.async.wait_group 0;" ::: "memory");
        }
        __syncthreads();

        const char* As = sm + (it & 1) * 16384;
        const char* Bs = As + 8192;

        #pragma unroll
        for (int s = 0; s < 2; s++) {
            uint32_t afrag[4][4], bfrag[4][2];
            #pragma unroll
            for (int mf = 0; mf < 4; mf++)
                #pragma unroll
                for (int r = 0; r < 4; r++) {
                    const int ch = (s * 2 + (r >> 1)) ^ achunk[mf][r];
                    afrag[mf][r] = *(const uint32_t*)(As + arow64[mf][r] + (ch << 4));
                }
            #pragma unroll
            for (int nf = 0; nf < 4; nf++)
                #pragma unroll
                for (int r = 0; r < 2; r++) {
                    const int ch = (s * 2 + r) ^ bxor[nf];
                    bfrag[nf][r] = *(const uint32_t*)(Bs + brow64[nf] + (ch << 4));
                }
            #pragma unroll
            for (int mf = 0; mf < 4; mf++)
                #pragma unroll
                for (int nf = 0; nf < 4; nf++)
                    mma16816(acc[mf][nf], afrag[mf], bfrag[nf]);
        }
        __syncthreads();
    }

    // ---- epilogue: bias + ReLU -> bf16 ----
    #pragma unroll
    for (int nf = 0; nf < 4; nf++) {
        const int col = bn + wn * 32 + nf * 8 + tig * 2;
        const float bv0 = bias[col], bv1 = bias[col + 1];
        #pragma unroll
        for (int mf = 0; mf < 4; mf++) {
            const int row0 = bm + wm * 64 + mf * 16 + gid;
            float v00 = fmaxf(acc[mf][nf][0] + bv0, 0.f);
            float v01 = fmaxf(acc[mf][nf][1] + bv1, 0.f);
            float v10 = fmaxf(acc[mf][nf][2] + bv0, 0.f);
            float v11 = fmaxf(acc[mf][nf][3] + bv1, 0.f);
            *(__nv_bfloat162*)(C + (size_t)row0 * Nout + col) =
                __floats2bfloat162_rn(v00, v01);
            *(__nv_bfloat162*)(C + (size_t)(row0 + 8) * Nout + col) =
                __floats2bfloat162_rn(v10, v11);
        }
    }
}

// ---------------------------------------------------------------------------
// Final: out = sigmoid(h3 @ Wd + bd + wide). One warp per batch row.
// ---------------------------------------------------------------------------
__global__ __launch_bounds__(256) void final_kernel(
    const float* __restrict__ Wd, const float* __restrict__ bd,
    float* __restrict__ out)
{
    const int warp = threadIdx.x >> 5;
    const int lane = threadIdx.x & 31;
    const int b    = blockIdx.x * 8 + warp;

    const __nv_bfloat16* h = g_h3b + (size_t)b * N3;
    float s = 0.f;
    #pragma unroll
    for (int i = lane; i < N3; i += 32) s += __bfloat162float(h[i]) * Wd[i];
    #pragma unroll
    for (int o = 16; o; o >>= 1) s += __shfl_xor_sync(0xFFFFFFFFu, s, o);

    if (lane == 0) {
        const float logit = s + bd[0] + g_wide[b];
        out[b] = 1.0f / (1.0f + expf(-logit));
    }
}

// ---------------------------------------------------------------------------
extern "C" void kernel_launch(void* const* d_in, const int* in_sizes, int n_in,
                              void* d_out, int out_size)
{
    (void)in_sizes; (void)n_in; (void)out_size;

    const int*   tok = (const int*)d_in[0];
    const int*   m1  = (const int*)d_in[1];
    const int*   m2  = (const int*)d_in[2];
    const int*   m3  = (const int*)d_in[3];
    const int*   o1  = (const int*)d_in[4];
    const int*   o2  = (const int*)d_in[5];
    const int*   o3  = (const int*)d_in[6];
    const int*   o4  = (const int*)d_in[7];
    const float* we  = (const float*)d_in[8];
    const float* em1 = (const float*)d_in[9];
    const float* em2 = (const float*)d_in[10];
    const float* em3 = (const float*)d_in[11];
    const float* eo1 = (const float*)d_in[12];
    const float* eo2 = (const float*)d_in[13];
    const float* eo3 = (const float*)d_in[14];
    const float* eo4 = (const float*)d_in[15];
    const float* wm1 = (const float*)d_in[16];
    const float* wm2 = (const float*)d_in[17];
    const float* wm3 = (const float*)d_in[18];
    const float* wo1 = (const float*)d_in[19];
    const float* wo2 = (const float*)d_in[20];
    const float* wo3 = (const float*)d_in[21];
    const float* wo4 = (const float*)d_in[22];
    const float* W1  = (const float*)d_in[23];
    const float* b1  = (const float*)d_in[24];
    const float* W2  = (const float*)d_in[25];
    const float* b2  = (const float*)d_in[26];
    const float* W3  = (const float*)d_in[27];
    const float* b3  = (const float*)d_in[28];
    const float* Wd  = (const float*)d_in[29];
    const float* bd  = (const float*)d_in[30];
    float* out = (float*)d_out;

    void *p_embB, *p_h1, *p_h2, *p_h3, *p_wt1, *p_wt2, *p_wt3;
    cudaGetSymbolAddress(&p_embB, g_embB);
    cudaGetSymbolAddress(&p_h1,   g_h1b);
    cudaGetSymbolAddress(&p_h2,   g_h2b);
    cudaGetSymbolAddress(&p_h3,   g_h3b);
    cudaGetSymbolAddress(&p_wt1,  g_Wt1);
    cudaGetSymbolAddress(&p_wt2,  g_Wt2);
    cudaGetSymbolAddress(&p_wt3,  g_Wt3);

    embed_kernel<<<B_SZ, 256>>>(tok, m1, m2, m3, o1, o2, o3, o4,
                                we, em1, em2, em3, eo1, eo2, eo3, eo4,
                                wm1, wm2, wm3, wo1, wo2, wo3, wo4);

    prep_wt_kernel<<<(N1 * K1P + 255) / 256, 256>>>(W1, (__nv_bfloat16*)p_wt1, K1, N1, K1P);
    prep_wt_kernel<<<(N2 * N1  + 255) / 256, 256>>>(W2, (__nv_bfloat16*)p_wt2, N1, N2, N1);
    prep_wt_kernel<<<(N3 * N2  + 255) / 256, 256>>>(W3, (__nv_bfloat16*)p_wt3, N2, N3, N2);

    gemm_tc_kernel<<<dim3(N1 / 128, B_SZ / 128), 256>>>(
        (const __nv_bfloat16*)p_embB, (const __nv_bfloat16*)p_wt1, b1,
        (__nv_bfloat16*)p_h1, N1, K1P);
    gemm_tc_kernel<<<dim3(N2 / 128, B_SZ / 128), 256>>>(
        (const __nv_bfloat16*)p_h1, (const __nv_bfloat16*)p_wt2, b2,
        (__nv_bfloat16*)p_h2, N2, N1);
    gemm_tc_kernel<<<dim3(N3 / 128, B_SZ / 128), 256>>>(
        (const __nv_bfloat16*)p_h2, (const __nv_bfloat16*)p_wt3, b3,
        (__nv_bfloat16*)p_h3, N3, N2);

    final_kernel<<<B_SZ / 8, 256>>>(Wd, bd, out);
}

// round 6
// speedup vs baseline: 4.5901x; 1.0721x over previous
#include <cuda_runtime.h>
#include <cuda_bf16.h>
#include <math.h>
#include <stdint.h>

// ---------------------------------------------------------------------------
// WideDeep round 5: round-4 kernel with the prep transpose bug fixed
// (tile fill is now transposed so the write phase indexes correctly).
// ---------------------------------------------------------------------------

#define B_SZ   8192
#define L_TOK  32
#define L_MH   20
#define EMB    64
#define TOK_D  300
#define K1     748
#define K1P    768
#define N1     1024
#define N2     512
#define N3     256

__device__ __align__(16) __nv_bfloat16 g_embB[B_SZ * K1P];
__device__ __align__(16) __nv_bfloat16 g_h1b [B_SZ * N1];
__device__ __align__(16) __nv_bfloat16 g_h2b [B_SZ * N2];
__device__ __align__(16) __nv_bfloat16 g_h3b [B_SZ * N3];
__device__ __align__(16) __nv_bfloat16 g_Wt1 [N1 * K1P];
__device__ __align__(16) __nv_bfloat16 g_Wt2 [N2 * N1];
__device__ __align__(16) __nv_bfloat16 g_Wt3 [N3 * N2];
__device__ float g_wide[B_SZ];

__device__ __forceinline__ uint32_t smem_u32(const void* p) {
    uint32_t a;
    asm("{ .reg .u64 t; cvta.to.shared.u64 t, %1; cvt.u32.u64 %0, t; }"
        : "=r"(a) : "l"(p));
    return a;
}
__device__ __forceinline__ uint32_t bf2_bits(float x, float y) {
    __nv_bfloat162 v = __floats2bfloat162_rn(x, y);
    return *(uint32_t*)&v;
}

// ---------------------------------------------------------------------------
// Kernel 1: embedding gather + mean + concat (bf16) + wide tower.
// One block per batch row, 256 threads, float4 gathers everywhere.
// ---------------------------------------------------------------------------
__global__ __launch_bounds__(256) void embed_kernel(
    const int* __restrict__ tok, const int* __restrict__ m1,
    const int* __restrict__ m2,  const int* __restrict__ m3,
    const int* __restrict__ o1,  const int* __restrict__ o2,
    const int* __restrict__ o3,  const int* __restrict__ o4,
    const float* __restrict__ we,
    const float* __restrict__ em1, const float* __restrict__ em2,
    const float* __restrict__ em3,
    const float* __restrict__ eo1, const float* __restrict__ eo2,
    const float* __restrict__ eo3, const float* __restrict__ eo4,
    const float* __restrict__ wm1, const float* __restrict__ wm2,
    const float* __restrict__ wm3,
    const float* __restrict__ wo1, const float* __restrict__ wo2,
    const float* __restrict__ wo3, const float* __restrict__ wo4)
{
    const int b   = blockIdx.x;
    const int tid = threadIdx.x;

    __shared__ int s_tok[L_TOK];
    __shared__ int s_m1[L_MH], s_m2[L_MH], s_m3[L_MH];
    __shared__ int s_oh[4];
    __shared__ float4 s_part[2][75];

    if (tid < 32)       s_tok[tid]      = tok[b * L_TOK + tid];
    else if (tid < 52)  s_m1[tid - 32]  = m1[b * L_MH + tid - 32];
    else if (tid < 72)  s_m2[tid - 52]  = m2[b * L_MH + tid - 52];
    else if (tid < 92)  s_m3[tid - 72]  = m3[b * L_MH + tid - 72];
    else if (tid == 92) s_oh[0] = o1[b];
    else if (tid == 93) s_oh[1] = o2[b];
    else if (tid == 94) s_oh[2] = o3[b];
    else if (tid == 95) s_oh[3] = o4[b];
    __syncthreads();

    __nv_bfloat16* eb = g_embB + (size_t)b * K1P;

    // ---- token bag mean (300 floats = 75 float4 chunks, 3 row groups) ----
    float4 acc = make_float4(0.f, 0.f, 0.f, 0.f);
    if (tid < 225) {
        const int c = tid % 75, g = tid / 75;
        const int j0 = g * 11, j1 = (g < 2) ? j0 + 11 : 32;
        for (int j = j0; j < j1; j++) {
            const float4 v = *(const float4*)(we + (size_t)s_tok[j] * TOK_D + c * 4);
            acc.x += v.x; acc.y += v.y; acc.z += v.z; acc.w += v.w;
        }
        if (g > 0) s_part[g - 1][c] = acc;
    }

    if (tid >= 228 && tid < 233) {            // zero-pad [748,768): 5 x 8B
        ((uint2*)(eb + K1))[tid - 228] = make_uint2(0u, 0u);
    }

    __syncthreads();

    if (tid < 75) {
        float4 t = acc;
        const float4 p0 = s_part[0][tid], p1 = s_part[1][tid];
        t.x = (t.x + p0.x + p1.x) * (1.0f / 32.0f);
        t.y = (t.y + p0.y + p1.y) * (1.0f / 32.0f);
        t.z = (t.z + p0.z + p1.z) * (1.0f / 32.0f);
        t.w = (t.w + p0.w + p1.w) * (1.0f / 32.0f);
        ((uint2*)eb)[tid] = make_uint2(bf2_bits(t.x, t.y), bf2_bits(t.z, t.w));
    } else if (tid >= 80 && tid < 128) {      // mh fields: 3 fields x 16 chunks
        const int f = (tid - 80) >> 4, c = (tid - 80) & 15;
        const float* tab = (f == 0) ? em1 : (f == 1) ? em2 : em3;
        const int* sidx = (f == 0) ? s_m1 : (f == 1) ? s_m2 : s_m3;
        float4 s = make_float4(0.f, 0.f, 0.f, 0.f);
        #pragma unroll
        for (int j = 0; j < L_MH; j++) {
            const float4 v = *(const float4*)(tab + (size_t)sidx[j] * EMB + c * 4);
            s.x += v.x; s.y += v.y; s.z += v.z; s.w += v.w;
        }
        __nv_bfloat16* dst = eb + 300 + f * 64 + c * 4;
        *(uint2*)dst = make_uint2(bf2_bits(s.x * 0.05f, s.y * 0.05f),
                                  bf2_bits(s.z * 0.05f, s.w * 0.05f));
    } else if (tid >= 128 && tid < 192) {     // oh fields: 4 fields x 16 chunks
        const int f = (tid - 128) >> 4, c = (tid - 128) & 15;
        const float* tab = (f == 0) ? eo1 : (f == 1) ? eo2 : (f == 2) ? eo3 : eo4;
        const float4 v = *(const float4*)(tab + (size_t)s_oh[f] * EMB + c * 4);
        __nv_bfloat16* dst = eb + 492 + f * 64 + c * 4;
        *(uint2*)dst = make_uint2(bf2_bits(v.x, v.y), bf2_bits(v.z, v.w));
    } else if (tid >= 192 && tid < 224) {     // wide tower: warp 6
        const int lane = tid - 192;
        float s = 0.f;
        if (lane < L_MH)
            s = wm1[s_m1[lane]] + wm2[s_m2[lane]] + wm3[s_m3[lane]];
        #pragma unroll
        for (int o = 16; o; o >>= 1) s += __shfl_xor_sync(0xFFFFFFFFu, s, o);
        if (lane == 0) {
            s += wo1[s_oh[0]] + wo2[s_oh[1]] + wo3[s_oh[2]] + wo4[s_oh[3]];
            g_wide[b] = s;
        }
    }
}

// ---------------------------------------------------------------------------
// Prep (single launch): W[K,N] fp32 -> Wt[N,Kpad] bf16, 32x32 smem tiles,
// coalesced reads AND writes.
// FIX vs round 4: tile is filled TRANSPOSED (tile[n_local][k_local]) so the
// write phase's tile[n][2p] reads produce Wt[n][k] = W[k][n].
// ---------------------------------------------------------------------------
__global__ __launch_bounds__(256) void prep_all_kernel(
    const float* __restrict__ W1, const float* __restrict__ W2,
    const float* __restrict__ W3,
    __nv_bfloat16* __restrict__ Wt1, __nv_bfloat16* __restrict__ Wt2,
    __nv_bfloat16* __restrict__ Wt3)
{
    __shared__ float tile[32][33];
    const int bid = blockIdx.x, tid = threadIdx.x;

    const float* W; __nv_bfloat16* Wt; int K, N, Kpad, t;
    if (bid < 768)       { W = W1; Wt = Wt1; K = K1; N = N1; Kpad = K1P; t = bid; }
    else if (bid < 1280) { W = W2; Wt = Wt2; K = N1; N = N2; Kpad = N1;  t = bid - 768; }
    else                 { W = W3; Wt = Wt3; K = N2; N = N3; Kpad = N2;  t = bid - 1280; }

    const int ktiles = Kpad >> 5;
    const int tk = t % ktiles, tn = t / ktiles;
    const int tx = tid & 31, ty = tid >> 5;

    #pragma unroll
    for (int i = 0; i < 4; i++) {
        const int k = tk * 32 + ty + i * 8;
        // tile[n_local][k_local]  (transposed store; read is coalesced on tx=n)
        tile[tx][ty + i * 8] = (k < K) ? W[(size_t)k * N + tn * 32 + tx] : 0.f;
    }
    __syncthreads();

    const int p = tid & 15;
    #pragma unroll
    for (int h = 0; h < 2; h++) {
        const int n = (tid >> 4) + 16 * h;
        const uint32_t v = bf2_bits(tile[n][2 * p], tile[n][2 * p + 1]);
        *(uint32_t*)(Wt + (size_t)(tn * 32 + n) * Kpad + tk * 32 + p * 2) = v;
    }
}

// ---------------------------------------------------------------------------
// Tensor-core GEMM: C = relu(A[M,K] @ Bt[N,K]^T + bias) -> bf16
// 128x128x32 CTA tile, 256 thr (2x4 warps, 64x32 warp tile), mma m16n8k16,
// 3-stage cp.async pipeline, one __syncthreads per k-iter, XOR-swizzled smem.
// ---------------------------------------------------------------------------
__device__ __forceinline__ void mma16816(float c[4], const uint32_t a[4],
                                         const uint32_t b[2])
{
    asm volatile(
        "mma.sync.aligned.m16n8k16.row.col.f32.bf16.bf16.f32 "
        "{%0,%1,%2,%3}, {%4,%5,%6,%7}, {%8,%9}, {%0,%1,%2,%3};"
        : "+f"(c[0]), "+f"(c[1]), "+f"(c[2]), "+f"(c[3])
        : "r"(a[0]), "r"(a[1]), "r"(a[2]), "r"(a[3]), "r"(b[0]), "r"(b[1]));
}

__global__ __launch_bounds__(256, 2) void gemm_tc_kernel(
    const __nv_bfloat16* __restrict__ A, const __nv_bfloat16* __restrict__ Bt,
    const float* __restrict__ bias, __nv_bfloat16* __restrict__ C,
    int Nout, int K)
{
    __shared__ __align__(1024) char sm[3 * 16384];   // 3 stages x (A 8K + B 8K)

    const int tid  = threadIdx.x;
    const int lane = tid & 31, warp = tid >> 5;
    const int wm   = warp & 1;
    const int wn   = warp >> 1;
    const int gid  = lane >> 2;
    const int tig  = lane & 3;
    const int bm   = blockIdx.y * 128, bn = blockIdx.x * 128;

    int offA[2], gA[2], gB[2];
    #pragma unroll
    for (int j = 0; j < 2; j++) {
        const int c = tid + j * 256;
        const int r = c >> 2, ch = c & 3;
        offA[j] = r * 64 + ((ch ^ ((r >> 1) & 3)) << 4);
        gA[j]   = (bm + r) * K + ch * 8;
        gB[j]   = (bn + r) * K + ch * 8;
    }

    const int NIT = K >> 5;

    uint32_t arow64[4][4]; int achunk[4][4];
    #pragma unroll
    for (int mf = 0; mf < 4; mf++)
        #pragma unroll
        for (int r = 0; r < 4; r++) {
            const int row = wm * 64 + mf * 16 + gid + (r & 1) * 8;
            arow64[mf][r] = row * 64 + tig * 4;
            achunk[mf][r] = ((row >> 1) & 3);
        }
    uint32_t brow64[4]; int bxor[4];
    #pragma unroll
    for (int nf = 0; nf < 4; nf++) {
        const int row = wn * 32 + nf * 8 + gid;
        brow64[nf] = row * 64 + tig * 4;
        bxor[nf]   = ((row >> 1) & 3);
    }

    float acc[4][4][4];
    #pragma unroll
    for (int mf = 0; mf < 4; mf++)
        #pragma unroll
        for (int nf = 0; nf < 4; nf++)
            #pragma unroll
            for (int i = 0; i < 4; i++) acc[mf][nf][i] = 0.f;

    #define PREFETCH(stage, kofs)                                              \
        do {                                                                   \
            char* _s = sm + (stage) * 16384;                                   \
            _Pragma("unroll")                                                  \
            for (int _j = 0; _j < 2; _j++) {                                   \
                uint32_t _da = smem_u32(_s + offA[_j]);                        \
                uint32_t _db = smem_u32(_s + 8192 + offA[_j]);                 \
                asm volatile("cp.async.cg.shared.global [%0], [%1], 16;"       \
                             :: "r"(_da), "l"(A + gA[_j] + (kofs)) : "memory");\
                asm volatile("cp.async.cg.shared.global [%0], [%1], 16;"       \
                             :: "r"(_db), "l"(Bt + gB[_j] + (kofs)) : "memory");\
            }                                                                  \
        } while (0)

    PREFETCH(0, 0);
    asm volatile("cp.async.commit_group;" ::: "memory");
    PREFETCH(1, 32);
    asm volatile("cp.async.commit_group;" ::: "memory");

    for (int it = 0; it < NIT; it++) {
        asm volatile("cp.async.wait_group 1;" ::: "memory");
        __syncthreads();

        if (it + 2 < NIT) {
            const int st = it + 2;
            PREFETCH(st % 3, st * 32);
        }
        asm volatile("cp.async.commit_group;" ::: "memory");

        const char* As = sm + (it % 3) * 16384;
        const char* Bs = As + 8192;

        #pragma unroll
        for (int s = 0; s < 2; s++) {
            uint32_t afrag[4][4], bfrag[4][2];
            #pragma unroll
            for (int mf = 0; mf < 4; mf++)
                #pragma unroll
                for (int r = 0; r < 4; r++) {
                    const int ch = (s * 2 + (r >> 1)) ^ achunk[mf][r];
                    afrag[mf][r] = *(const uint32_t*)(As + arow64[mf][r] + (ch << 4));
                }
            #pragma unroll
            for (int nf = 0; nf < 4; nf++)
                #pragma unroll
                for (int r = 0; r < 2; r++) {
                    const int ch = (s * 2 + r) ^ bxor[nf];
                    bfrag[nf][r] = *(const uint32_t*)(Bs + brow64[nf] + (ch << 4));
                }
            #pragma unroll
            for (int mf = 0; mf < 4; mf++)
                #pragma unroll
                for (int nf = 0; nf < 4; nf++)
                    mma16816(acc[mf][nf], afrag[mf], bfrag[nf]);
        }
    }
    #undef PREFETCH

    #pragma unroll
    for (int nf = 0; nf < 4; nf++) {
        const int col = bn + wn * 32 + nf * 8 + tig * 2;
        const float bv0 = bias[col], bv1 = bias[col + 1];
        #pragma unroll
        for (int mf = 0; mf < 4; mf++) {
            const int row0 = bm + wm * 64 + mf * 16 + gid;
            const float v00 = fmaxf(acc[mf][nf][0] + bv0, 0.f);
            const float v01 = fmaxf(acc[mf][nf][1] + bv1, 0.f);
            const float v10 = fmaxf(acc[mf][nf][2] + bv0, 0.f);
            const float v11 = fmaxf(acc[mf][nf][3] + bv1, 0.f);
            *(__nv_bfloat162*)(C + (size_t)row0 * Nout + col) =
                __floats2bfloat162_rn(v00, v01);
            *(__nv_bfloat162*)(C + (size_t)(row0 + 8) * Nout + col) =
                __floats2bfloat162_rn(v10, v11);
        }
    }
}

// ---------------------------------------------------------------------------
// Final: out = sigmoid(h3 @ Wd + bd + wide). One warp per row, vectorized.
// ---------------------------------------------------------------------------
__global__ __launch_bounds__(256) void final_kernel(
    const float* __restrict__ Wd, const float* __restrict__ bd,
    float* __restrict__ out)
{
    const int warp = threadIdx.x >> 5;
    const int lane = threadIdx.x & 31;
    const int b    = blockIdx.x * 8 + warp;

    const __nv_bfloat16* h = g_h3b + (size_t)b * N3;
    const uint4 hv = ((const uint4*)h)[lane];          // 8 bf16
    const float4 w0 = ((const float4*)Wd)[lane * 2];
    const float4 w1 = ((const float4*)Wd)[lane * 2 + 1];

    const __nv_bfloat162* hp = (const __nv_bfloat162*)&hv;
    float s = 0.f;
    float2 p;
    p = __bfloat1622float2(hp[0]); s += p.x * w0.x + p.y * w0.y;
    p = __bfloat1622float2(hp[1]); s += p.x * w0.z + p.y * w0.w;
    p = __bfloat1622float2(hp[2]); s += p.x * w1.x + p.y * w1.y;
    p = __bfloat1622float2(hp[3]); s += p.x * w1.z + p.y * w1.w;

    #pragma unroll
    for (int o = 16; o; o >>= 1) s += __shfl_xor_sync(0xFFFFFFFFu, s, o);

    if (lane == 0) {
        const float logit = s + bd[0] + g_wide[b];
        out[b] = 1.0f / (1.0f + expf(-logit));
    }
}

// ---------------------------------------------------------------------------
extern "C" void kernel_launch(void* const* d_in, const int* in_sizes, int n_in,
                              void* d_out, int out_size)
{
    (void)in_sizes; (void)n_in; (void)out_size;

    const int*   tok = (const int*)d_in[0];
    const int*   m1  = (const int*)d_in[1];
    const int*   m2  = (const int*)d_in[2];
    const int*   m3  = (const int*)d_in[3];
    const int*   o1  = (const int*)d_in[4];
    const int*   o2  = (const int*)d_in[5];
    const int*   o3  = (const int*)d_in[6];
    const int*   o4  = (const int*)d_in[7];
    const float* we  = (const float*)d_in[8];
    const float* em1 = (const float*)d_in[9];
    const float* em2 = (const float*)d_in[10];
    const float* em3 = (const float*)d_in[11];
    const float* eo1 = (const float*)d_in[12];
    const float* eo2 = (const float*)d_in[13];
    const float* eo3 = (const float*)d_in[14];
    const float* eo4 = (const float*)d_in[15];
    const float* wm1 = (const float*)d_in[16];
    const float* wm2 = (const float*)d_in[17];
    const float* wm3 = (const float*)d_in[18];
    const float* wo1 = (const float*)d_in[19];
    const float* wo2 = (const float*)d_in[20];
    const float* wo3 = (const float*)d_in[21];
    const float* wo4 = (const float*)d_in[22];
    const float* W1  = (const float*)d_in[23];
    const float* b1  = (const float*)d_in[24];
    const float* W2  = (const float*)d_in[25];
    const float* b2  = (const float*)d_in[26];
    const float* W3  = (const float*)d_in[27];
    const float* b3  = (const float*)d_in[28];
    const float* Wd  = (const float*)d_in[29];
    const float* bd  = (const float*)d_in[30];
    float* out = (float*)d_out;

    void *p_embB, *p_h1, *p_h2, *p_h3, *p_wt1, *p_wt2, *p_wt3;
    cudaGetSymbolAddress(&p_embB, g_embB);
    cudaGetSymbolAddress(&p_h1,   g_h1b);
    cudaGetSymbolAddress(&p_h2,   g_h2b);
    cudaGetSymbolAddress(&p_h3,   g_h3b);
    cudaGetSymbolAddress(&p_wt1,  g_Wt1);
    cudaGetSymbolAddress(&p_wt2,  g_Wt2);
    cudaGetSymbolAddress(&p_wt3,  g_Wt3);

    embed_kernel<<<B_SZ, 256>>>(tok, m1, m2, m3, o1, o2, o3, o4,
                                we, em1, em2, em3, eo1, eo2, eo3, eo4,
                                wm1, wm2, wm3, wo1, wo2, wo3, wo4);

    prep_all_kernel<<<768 + 512 + 128, 256>>>(
        W1, W2, W3, (__nv_bfloat16*)p_wt1, (__nv_bfloat16*)p_wt2,
        (__nv_bfloat16*)p_wt3);

    gemm_tc_kernel<<<dim3(N1 / 128, B_SZ / 128), 256>>>(
        (const __nv_bfloat16*)p_embB, (const __nv_bfloat16*)p_wt1, b1,
        (__nv_bfloat16*)p_h1, N1, K1P);
    gemm_tc_kernel<<<dim3(N2 / 128, B_SZ / 128), 256>>>(
        (const __nv_bfloat16*)p_h1, (const __nv_bfloat16*)p_wt2, b2,
        (__nv_bfloat16*)p_h2, N2, N1);
    gemm_tc_kernel<<<dim3(N3 / 128, B_SZ / 128), 256>>>(
        (const __nv_bfloat16*)p_h2, (const __nv_bfloat16*)p_wt3, b3,
        (__nv_bfloat16*)p_h3, N3, N2);

    final_kernel<<<B_SZ / 8, 256>>>(Wd, bd, out);
}

// round 7
// speedup vs baseline: 5.2165x; 1.1365x over previous
#include <cuda_runtime.h>
#include <cuda_bf16.h>
#include <math.h>
#include <stdint.h>

// ---------------------------------------------------------------------------
// WideDeep round 6: ldmatrix fragment loads in the GEMM mainloop (4x fewer
// shared-load instructions), embed+prep fused into one launch.
// ---------------------------------------------------------------------------

#define B_SZ   8192
#define L_TOK  32
#define L_MH   20
#define EMB    64
#define TOK_D  300
#define K1     748
#define K1P    768
#define N1     1024
#define N2     512
#define N3     256

__device__ __align__(16) __nv_bfloat16 g_embB[B_SZ * K1P];
__device__ __align__(16) __nv_bfloat16 g_h1b [B_SZ * N1];
__device__ __align__(16) __nv_bfloat16 g_h2b [B_SZ * N2];
__device__ __align__(16) __nv_bfloat16 g_h3b [B_SZ * N3];
__device__ __align__(16) __nv_bfloat16 g_Wt1 [N1 * K1P];
__device__ __align__(16) __nv_bfloat16 g_Wt2 [N2 * N1];
__device__ __align__(16) __nv_bfloat16 g_Wt3 [N3 * N2];
__device__ float g_wide[B_SZ];

__device__ __forceinline__ uint32_t smem_u32(const void* p) {
    uint32_t a;
    asm("{ .reg .u64 t; cvta.to.shared.u64 t, %1; cvt.u32.u64 %0, t; }"
        : "=r"(a) : "l"(p));
    return a;
}
__device__ __forceinline__ uint32_t bf2_bits(float x, float y) {
    __nv_bfloat162 v = __floats2bfloat162_rn(x, y);
    return *(uint32_t*)&v;
}

// ---------------------------------------------------------------------------
// Fused kernel 1: blocks [0, 8192) embed; blocks [8192, 9600) weight prep.
// ---------------------------------------------------------------------------
__global__ __launch_bounds__(256) void embed_prep_kernel(
    const int* __restrict__ tok, const int* __restrict__ m1,
    const int* __restrict__ m2,  const int* __restrict__ m3,
    const int* __restrict__ o1,  const int* __restrict__ o2,
    const int* __restrict__ o3,  const int* __restrict__ o4,
    const float* __restrict__ we,
    const float* __restrict__ em1, const float* __restrict__ em2,
    const float* __restrict__ em3,
    const float* __restrict__ eo1, const float* __restrict__ eo2,
    const float* __restrict__ eo3, const float* __restrict__ eo4,
    const float* __restrict__ wm1, const float* __restrict__ wm2,
    const float* __restrict__ wm3,
    const float* __restrict__ wo1, const float* __restrict__ wo2,
    const float* __restrict__ wo3, const float* __restrict__ wo4,
    const float* __restrict__ W1, const float* __restrict__ W2,
    const float* __restrict__ W3)
{
    const int tid = threadIdx.x;

    if (blockIdx.x >= B_SZ) {
        // ------------------ weight transpose prep ------------------
        __shared__ float tile[32][33];
        const int bid = blockIdx.x - B_SZ;

        const float* W; __nv_bfloat16* Wt; int K, N, Kpad, t;
        if (bid < 768)       { W = W1; Wt = g_Wt1; K = K1; N = N1; Kpad = K1P; t = bid; }
        else if (bid < 1280) { W = W2; Wt = g_Wt2; K = N1; N = N2; Kpad = N1;  t = bid - 768; }
        else                 { W = W3; Wt = g_Wt3; K = N2; N = N3; Kpad = N2;  t = bid - 1280; }

        const int ktiles = Kpad >> 5;
        const int tk = t % ktiles, tn = t / ktiles;
        const int tx = tid & 31, ty = tid >> 5;

        #pragma unroll
        for (int i = 0; i < 4; i++) {
            const int k = tk * 32 + ty + i * 8;
            tile[tx][ty + i * 8] = (k < K) ? W[(size_t)k * N + tn * 32 + tx] : 0.f;
        }
        __syncthreads();

        const int p = tid & 15;
        #pragma unroll
        for (int h = 0; h < 2; h++) {
            const int n = (tid >> 4) + 16 * h;
            const uint32_t v = bf2_bits(tile[n][2 * p], tile[n][2 * p + 1]);
            *(uint32_t*)(Wt + (size_t)(tn * 32 + n) * Kpad + tk * 32 + p * 2) = v;
        }
        return;
    }

    // ------------------ embedding gather + concat ------------------
    const int b = blockIdx.x;

    __shared__ int s_tok[L_TOK];
    __shared__ int s_m1[L_MH], s_m2[L_MH], s_m3[L_MH];
    __shared__ int s_oh[4];
    __shared__ float4 s_part[2][75];

    if (tid < 32)       s_tok[tid]      = tok[b * L_TOK + tid];
    else if (tid < 52)  s_m1[tid - 32]  = m1[b * L_MH + tid - 32];
    else if (tid < 72)  s_m2[tid - 52]  = m2[b * L_MH + tid - 52];
    else if (tid < 92)  s_m3[tid - 72]  = m3[b * L_MH + tid - 72];
    else if (tid == 92) s_oh[0] = o1[b];
    else if (tid == 93) s_oh[1] = o2[b];
    else if (tid == 94) s_oh[2] = o3[b];
    else if (tid == 95) s_oh[3] = o4[b];
    __syncthreads();

    __nv_bfloat16* eb = g_embB + (size_t)b * K1P;

    float4 acc = make_float4(0.f, 0.f, 0.f, 0.f);
    if (tid < 225) {
        const int c = tid % 75, g = tid / 75;
        const int j0 = g * 11, j1 = (g < 2) ? j0 + 11 : 32;
        for (int j = j0; j < j1; j++) {
            const float4 v = *(const float4*)(we + (size_t)s_tok[j] * TOK_D + c * 4);
            acc.x += v.x; acc.y += v.y; acc.z += v.z; acc.w += v.w;
        }
        if (g > 0) s_part[g - 1][c] = acc;
    }

    if (tid >= 228 && tid < 233)
        ((uint2*)(eb + K1))[tid - 228] = make_uint2(0u, 0u);

    __syncthreads();

    if (tid < 75) {
        float4 t = acc;
        const float4 p0 = s_part[0][tid], p1 = s_part[1][tid];
        t.x = (t.x + p0.x + p1.x) * (1.0f / 32.0f);
        t.y = (t.y + p0.y + p1.y) * (1.0f / 32.0f);
        t.z = (t.z + p0.z + p1.z) * (1.0f / 32.0f);
        t.w = (t.w + p0.w + p1.w) * (1.0f / 32.0f);
        ((uint2*)eb)[tid] = make_uint2(bf2_bits(t.x, t.y), bf2_bits(t.z, t.w));
    } else if (tid >= 80 && tid < 128) {
        const int f = (tid - 80) >> 4, c = (tid - 80) & 15;
        const float* tab = (f == 0) ? em1 : (f == 1) ? em2 : em3;
        const int* sidx = (f == 0) ? s_m1 : (f == 1) ? s_m2 : s_m3;
        float4 s = make_float4(0.f, 0.f, 0.f, 0.f);
        #pragma unroll
        for (int j = 0; j < L_MH; j++) {
            const float4 v = *(const float4*)(tab + (size_t)sidx[j] * EMB + c * 4);
            s.x += v.x; s.y += v.y; s.z += v.z; s.w += v.w;
        }
        __nv_bfloat16* dst = eb + 300 + f * 64 + c * 4;
        *(uint2*)dst = make_uint2(bf2_bits(s.x * 0.05f, s.y * 0.05f),
                                  bf2_bits(s.z * 0.05f, s.w * 0.05f));
    } else if (tid >= 128 && tid < 192) {
        const int f = (tid - 128) >> 4, c = (tid - 128) & 15;
        const float* tab = (f == 0) ? eo1 : (f == 1) ? eo2 : (f == 2) ? eo3 : eo4;
        const float4 v = *(const float4*)(tab + (size_t)s_oh[f] * EMB + c * 4);
        __nv_bfloat16* dst = eb + 492 + f * 64 + c * 4;
        *(uint2*)dst = make_uint2(bf2_bits(v.x, v.y), bf2_bits(v.z, v.w));
    } else if (tid >= 192 && tid < 224) {
        const int lane = tid - 192;
        float s = 0.f;
        if (lane < L_MH)
            s = wm1[s_m1[lane]] + wm2[s_m2[lane]] + wm3[s_m3[lane]];
        #pragma unroll
        for (int o = 16; o; o >>= 1) s += __shfl_xor_sync(0xFFFFFFFFu, s, o);
        if (lane == 0) {
            s += wo1[s_oh[0]] + wo2[s_oh[1]] + wo3[s_oh[2]] + wo4[s_oh[3]];
            g_wide[b] = s;
        }
    }
}

// ---------------------------------------------------------------------------
// Tensor-core GEMM: C = relu(A[M,K] @ Bt[N,K]^T + bias) -> bf16
// 128x128x32 CTA tile, 256 thr (2x4 warps, 64x32 warp tile), mma m16n8k16,
// 3-stage cp.async pipeline, ldmatrix.x4 fragment loads, XOR-swizzled smem.
// ---------------------------------------------------------------------------
__device__ __forceinline__ void mma16816(float c[4], const uint32_t a[4],
                                         const uint32_t b[2])
{
    asm volatile(
        "mma.sync.aligned.m16n8k16.row.col.f32.bf16.bf16.f32 "
        "{%0,%1,%2,%3}, {%4,%5,%6,%7}, {%8,%9}, {%0,%1,%2,%3};"
        : "+f"(c[0]), "+f"(c[1]), "+f"(c[2]), "+f"(c[3])
        : "r"(a[0]), "r"(a[1]), "r"(a[2]), "r"(a[3]), "r"(b[0]), "r"(b[1]));
}

__global__ __launch_bounds__(256, 2) void gemm_tc_kernel(
    const __nv_bfloat16* __restrict__ A, const __nv_bfloat16* __restrict__ Bt,
    const float* __restrict__ bias, __nv_bfloat16* __restrict__ C,
    int Nout, int K)
{
    __shared__ __align__(1024) char sm[3 * 16384];   // 3 stages x (A 8K + B 8K)

    const int tid  = threadIdx.x;
    const int lane = tid & 31, warp = tid >> 5;
    const int wm   = warp & 1;
    const int wn   = warp >> 1;
    const int gid  = lane >> 2;
    const int tig  = lane & 3;
    const int bm   = blockIdx.y * 128, bn = blockIdx.x * 128;

    // cp.async producer assignments
    int offA[2], gA[2], gB[2];
    #pragma unroll
    for (int j = 0; j < 2; j++) {
        const int c = tid + j * 256;
        const int r = c >> 2, ch = c & 3;
        offA[j] = r * 64 + ((ch ^ ((r >> 1) & 3)) << 4);
        gA[j]   = (bm + r) * K + ch * 8;
        gB[j]   = (bn + r) * K + ch * 8;
    }

    const int NIT = K >> 5;

    // ldmatrix per-lane addressing
    //   A (reg order a0..a3 = {+0/klo, +8/klo, +0/khi, +8/khi}):
    //     rowoff = (q&1)*8 + r8, chunkbit = q>>1
    //   B (reg order {nf.b0, nf.b1, nf+1.b0, nf+1.b1}):
    //     rowoff = (q>>1)*8 + r8, chunkbit = q&1
    const int q = lane >> 3, r8 = lane & 7;
    const int qa = q >> 1, qb = q & 1;
    uint32_t arow64[4]; int akey[4];
    #pragma unroll
    for (int mf = 0; mf < 4; mf++) {
        const int row = wm * 64 + mf * 16 + (q & 1) * 8 + r8;
        arow64[mf] = row * 64;
        akey[mf]   = (row >> 1) & 3;
    }
    uint32_t brow64[2]; int bkey[2];
    #pragma unroll
    for (int g = 0; g < 2; g++) {
        const int row = wn * 32 + g * 16 + (q >> 1) * 8 + r8;
        brow64[g] = row * 64;
        bkey[g]   = (row >> 1) & 3;
    }

    float acc[4][4][4];
    #pragma unroll
    for (int mf = 0; mf < 4; mf++)
        #pragma unroll
        for (int nf = 0; nf < 4; nf++)
            #pragma unroll
            for (int i = 0; i < 4; i++) acc[mf][nf][i] = 0.f;

    #define PREFETCH(stage, kofs)                                              \
        do {                                                                   \
            char* _s = sm + (stage) * 16384;                                   \
            _Pragma("unroll")                                                  \
            for (int _j = 0; _j < 2; _j++) {                                   \
                uint32_t _da = smem_u32(_s + offA[_j]);                        \
                uint32_t _db = smem_u32(_s + 8192 + offA[_j]);                 \
                asm volatile("cp.async.cg.shared.global [%0], [%1], 16;"       \
                             :: "r"(_da), "l"(A + gA[_j] + (kofs)) : "memory");\
                asm volatile("cp.async.cg.shared.global [%0], [%1], 16;"       \
                             :: "r"(_db), "l"(Bt + gB[_j] + (kofs)) : "memory");\
            }                                                                  \
        } while (0)

    PREFETCH(0, 0);
    asm volatile("cp.async.commit_group;" ::: "memory");
    PREFETCH(1, 32);
    asm volatile("cp.async.commit_group;" ::: "memory");

    for (int it = 0; it < NIT; it++) {
        asm volatile("cp.async.wait_group 1;" ::: "memory");
        __syncthreads();

        if (it + 2 < NIT) {
            const int st = it + 2;
            PREFETCH(st % 3, st * 32);
        }
        asm volatile("cp.async.commit_group;" ::: "memory");

        const uint32_t AsU = smem_u32(sm + (it % 3) * 16384);
        const uint32_t BsU = AsU + 8192;

        #pragma unroll
        for (int s = 0; s < 2; s++) {
            uint32_t af[4][4], bf[4][2];
            #pragma unroll
            for (int mf = 0; mf < 4; mf++) {
                const uint32_t addr =
                    AsU + arow64[mf] + ((((s << 1) + qa) ^ akey[mf]) << 4);
                asm volatile(
                    "ldmatrix.sync.aligned.m8n8.x4.shared.b16 {%0,%1,%2,%3}, [%4];"
                    : "=r"(af[mf][0]), "=r"(af[mf][1]),
                      "=r"(af[mf][2]), "=r"(af[mf][3])
                    : "r"(addr));
            }
            #pragma unroll
            for (int g = 0; g < 2; g++) {
                const uint32_t addr =
                    BsU + brow64[g] + ((((s << 1) + qb) ^ bkey[g]) << 4);
                asm volatile(
                    "ldmatrix.sync.aligned.m8n8.x4.shared.b16 {%0,%1,%2,%3}, [%4];"
                    : "=r"(bf[2 * g][0]), "=r"(bf[2 * g][1]),
                      "=r"(bf[2 * g + 1][0]), "=r"(bf[2 * g + 1][1])
                    : "r"(addr));
            }
            #pragma unroll
            for (int mf = 0; mf < 4; mf++)
                #pragma unroll
                for (int nf = 0; nf < 4; nf++)
                    mma16816(acc[mf][nf], af[mf], bf[nf]);
        }
    }
    #undef PREFETCH

    // epilogue: bias + ReLU -> bf16
    #pragma unroll
    for (int nf = 0; nf < 4; nf++) {
        const int col = bn + wn * 32 + nf * 8 + tig * 2;
        const float bv0 = bias[col], bv1 = bias[col + 1];
        #pragma unroll
        for (int mf = 0; mf < 4; mf++) {
            const int row0 = bm + wm * 64 + mf * 16 + gid;
            const float v00 = fmaxf(acc[mf][nf][0] + bv0, 0.f);
            const float v01 = fmaxf(acc[mf][nf][1] + bv1, 0.f);
            const float v10 = fmaxf(acc[mf][nf][2] + bv0, 0.f);
            const float v11 = fmaxf(acc[mf][nf][3] + bv1, 0.f);
            *(__nv_bfloat162*)(C + (size_t)row0 * Nout + col) =
                __floats2bfloat162_rn(v00, v01);
            *(__nv_bfloat162*)(C + (size_t)(row0 + 8) * Nout + col) =
                __floats2bfloat162_rn(v10, v11);
        }
    }
}

// ---------------------------------------------------------------------------
// Final: out = sigmoid(h3 @ Wd + bd + wide). One warp per row, vectorized.
// ---------------------------------------------------------------------------
__global__ __launch_bounds__(256) void final_kernel(
    const float* __restrict__ Wd, const float* __restrict__ bd,
    float* __restrict__ out)
{
    const int warp = threadIdx.x >> 5;
    const int lane = threadIdx.x & 31;
    const int b    = blockIdx.x * 8 + warp;

    const __nv_bfloat16* h = g_h3b + (size_t)b * N3;
    const uint4 hv = ((const uint4*)h)[lane];
    const float4 w0 = ((const float4*)Wd)[lane * 2];
    const float4 w1 = ((const float4*)Wd)[lane * 2 + 1];

    const __nv_bfloat162* hp = (const __nv_bfloat162*)&hv;
    float s = 0.f;
    float2 p;
    p = __bfloat1622float2(hp[0]); s += p.x * w0.x + p.y * w0.y;
    p = __bfloat1622float2(hp[1]); s += p.x * w0.z + p.y * w0.w;
    p = __bfloat1622float2(hp[2]); s += p.x * w1.x + p.y * w1.y;
    p = __bfloat1622float2(hp[3]); s += p.x * w1.z + p.y * w1.w;

    #pragma unroll
    for (int o = 16; o; o >>= 1) s += __shfl_xor_sync(0xFFFFFFFFu, s, o);

    if (lane == 0) {
        const float logit = s + bd[0] + g_wide[b];
        out[b] = 1.0f / (1.0f + expf(-logit));
    }
}

// ---------------------------------------------------------------------------
extern "C" void kernel_launch(void* const* d_in, const int* in_sizes, int n_in,
                              void* d_out, int out_size)
{
    (void)in_sizes; (void)n_in; (void)out_size;

    const int*   tok = (const int*)d_in[0];
    const int*   m1  = (const int*)d_in[1];
    const int*   m2  = (const int*)d_in[2];
    const int*   m3  = (const int*)d_in[3];
    const int*   o1  = (const int*)d_in[4];
    const int*   o2  = (const int*)d_in[5];
    const int*   o3  = (const int*)d_in[6];
    const int*   o4  = (const int*)d_in[7];
    const float* we  = (const float*)d_in[8];
    const float* em1 = (const float*)d_in[9];
    const float* em2 = (const float*)d_in[10];
    const float* em3 = (const float*)d_in[11];
    const float* eo1 = (const float*)d_in[12];
    const float* eo2 = (const float*)d_in[13];
    const float* eo3 = (const float*)d_in[14];
    const float* eo4 = (const float*)d_in[15];
    const float* wm1 = (const float*)d_in[16];
    const float* wm2 = (const float*)d_in[17];
    const float* wm3 = (const float*)d_in[18];
    const float* wo1 = (const float*)d_in[19];
    const float* wo2 = (const float*)d_in[20];
    const float* wo3 = (const float*)d_in[21];
    const float* wo4 = (const float*)d_in[22];
    const float* W1  = (const float*)d_in[23];
    const float* b1  = (const float*)d_in[24];
    const float* W2  = (const float*)d_in[25];
    const float* b2  = (const float*)d_in[26];
    const float* W3  = (const float*)d_in[27];
    const float* b3  = (const float*)d_in[28];
    const float* Wd  = (const float*)d_in[29];
    const float* bd  = (const float*)d_in[30];
    float* out = (float*)d_out;

    void *p_embB, *p_h1, *p_h2, *p_h3, *p_wt1, *p_wt2, *p_wt3;
    cudaGetSymbolAddress(&p_embB, g_embB);
    cudaGetSymbolAddress(&p_h1,   g_h1b);
    cudaGetSymbolAddress(&p_h2,   g_h2b);
    cudaGetSymbolAddress(&p_h3,   g_h3b);
    cudaGetSymbolAddress(&p_wt1,  g_Wt1);
    cudaGetSymbolAddress(&p_wt2,  g_Wt2);
    cudaGetSymbolAddress(&p_wt3,  g_Wt3);

    embed_prep_kernel<<<B_SZ + 768 + 512 + 128, 256>>>(
        tok, m1, m2, m3, o1, o2, o3, o4,
        we, em1, em2, em3, eo1, eo2, eo3, eo4,
        wm1, wm2, wm3, wo1, wo2, wo3, wo4,
        W1, W2, W3);

    gemm_tc_kernel<<<dim3(N1 / 128, B_SZ / 128), 256>>>(
        (const __nv_bfloat16*)p_embB, (const __nv_bfloat16*)p_wt1, b1,
        (__nv_bfloat16*)p_h1, N1, K1P);
    gemm_tc_kernel<<<dim3(N2 / 128, B_SZ / 128), 256>>>(
        (const __nv_bfloat16*)p_h1, (const __nv_bfloat16*)p_wt2, b2,
        (__nv_bfloat16*)p_h2, N2, N1);
    gemm_tc_kernel<<<dim3(N3 / 128, B_SZ / 128), 256>>>(
        (const __nv_bfloat16*)p_h2, (const __nv_bfloat16*)p_wt3, b3,
        (__nv_bfloat16*)p_h3, N3, N2);

    final_kernel<<<B_SZ / 8, 256>>>(Wd, bd, out);
}

// round 8
// speedup vs baseline: 5.5224x; 1.0587x over previous
#include <cuda_runtime.h>
#include <cuda_bf16.h>
#include <math.h>
#include <stdint.h>

// ---------------------------------------------------------------------------
// WideDeep round 7: GEMM k-chunk 32 -> 64 (half the barriers/waits, double
// prefetch distance), SW128-style 8-chunk XOR swizzle, dynamic smem (96 KB).
// ---------------------------------------------------------------------------

#define B_SZ   8192
#define L_TOK  32
#define L_MH   20
#define EMB    64
#define TOK_D  300
#define K1     748
#define K1P    768
#define N1     1024
#define N2     512
#define N3     256

__device__ __align__(16) __nv_bfloat16 g_embB[B_SZ * K1P];
__device__ __align__(16) __nv_bfloat16 g_h1b [B_SZ * N1];
__device__ __align__(16) __nv_bfloat16 g_h2b [B_SZ * N2];
__device__ __align__(16) __nv_bfloat16 g_h3b [B_SZ * N3];
__device__ __align__(16) __nv_bfloat16 g_Wt1 [N1 * K1P];
__device__ __align__(16) __nv_bfloat16 g_Wt2 [N2 * N1];
__device__ __align__(16) __nv_bfloat16 g_Wt3 [N3 * N2];
__device__ float g_wide[B_SZ];

__device__ __forceinline__ uint32_t smem_u32(const void* p) {
    uint32_t a;
    asm("{ .reg .u64 t; cvta.to.shared.u64 t, %1; cvt.u32.u64 %0, t; }"
        : "=r"(a) : "l"(p));
    return a;
}
__device__ __forceinline__ uint32_t bf2_bits(float x, float y) {
    __nv_bfloat162 v = __floats2bfloat162_rn(x, y);
    return *(uint32_t*)&v;
}

// ---------------------------------------------------------------------------
// Fused kernel 1: blocks [0, 8192) embed; blocks [8192, 9600) weight prep.
// ---------------------------------------------------------------------------
__global__ __launch_bounds__(256) void embed_prep_kernel(
    const int* __restrict__ tok, const int* __restrict__ m1,
    const int* __restrict__ m2,  const int* __restrict__ m3,
    const int* __restrict__ o1,  const int* __restrict__ o2,
    const int* __restrict__ o3,  const int* __restrict__ o4,
    const float* __restrict__ we,
    const float* __restrict__ em1, const float* __restrict__ em2,
    const float* __restrict__ em3,
    const float* __restrict__ eo1, const float* __restrict__ eo2,
    const float* __restrict__ eo3, const float* __restrict__ eo4,
    const float* __restrict__ wm1, const float* __restrict__ wm2,
    const float* __restrict__ wm3,
    const float* __restrict__ wo1, const float* __restrict__ wo2,
    const float* __restrict__ wo3, const float* __restrict__ wo4,
    const float* __restrict__ W1, const float* __restrict__ W2,
    const float* __restrict__ W3)
{
    const int tid = threadIdx.x;

    if (blockIdx.x >= B_SZ) {
        __shared__ float tile[32][33];
        const int bid = blockIdx.x - B_SZ;

        const float* W; __nv_bfloat16* Wt; int K, N, Kpad, t;
        if (bid < 768)       { W = W1; Wt = g_Wt1; K = K1; N = N1; Kpad = K1P; t = bid; }
        else if (bid < 1280) { W = W2; Wt = g_Wt2; K = N1; N = N2; Kpad = N1;  t = bid - 768; }
        else                 { W = W3; Wt = g_Wt3; K = N2; N = N3; Kpad = N2;  t = bid - 1280; }

        const int ktiles = Kpad >> 5;
        const int tk = t % ktiles, tn = t / ktiles;
        const int tx = tid & 31, ty = tid >> 5;

        #pragma unroll
        for (int i = 0; i < 4; i++) {
            const int k = tk * 32 + ty + i * 8;
            tile[tx][ty + i * 8] = (k < K) ? W[(size_t)k * N + tn * 32 + tx] : 0.f;
        }
        __syncthreads();

        const int p = tid & 15;
        #pragma unroll
        for (int h = 0; h < 2; h++) {
            const int n = (tid >> 4) + 16 * h;
            const uint32_t v = bf2_bits(tile[n][2 * p], tile[n][2 * p + 1]);
            *(uint32_t*)(Wt + (size_t)(tn * 32 + n) * Kpad + tk * 32 + p * 2) = v;
        }
        return;
    }

    const int b = blockIdx.x;

    __shared__ int s_tok[L_TOK];
    __shared__ int s_m1[L_MH], s_m2[L_MH], s_m3[L_MH];
    __shared__ int s_oh[4];
    __shared__ float4 s_part[2][75];

    if (tid < 32)       s_tok[tid]      = tok[b * L_TOK + tid];
    else if (tid < 52)  s_m1[tid - 32]  = m1[b * L_MH + tid - 32];
    else if (tid < 72)  s_m2[tid - 52]  = m2[b * L_MH + tid - 52];
    else if (tid < 92)  s_m3[tid - 72]  = m3[b * L_MH + tid - 72];
    else if (tid == 92) s_oh[0] = o1[b];
    else if (tid == 93) s_oh[1] = o2[b];
    else if (tid == 94) s_oh[2] = o3[b];
    else if (tid == 95) s_oh[3] = o4[b];
    __syncthreads();

    __nv_bfloat16* eb = g_embB + (size_t)b * K1P;

    float4 acc = make_float4(0.f, 0.f, 0.f, 0.f);
    if (tid < 225) {
        const int c = tid % 75, g = tid / 75;
        const int j0 = g * 11, j1 = (g < 2) ? j0 + 11 : 32;
        for (int j = j0; j < j1; j++) {
            const float4 v = *(const float4*)(we + (size_t)s_tok[j] * TOK_D + c * 4);
            acc.x += v.x; acc.y += v.y; acc.z += v.z; acc.w += v.w;
        }
        if (g > 0) s_part[g - 1][c] = acc;
    }

    if (tid >= 228 && tid < 233)
        ((uint2*)(eb + K1))[tid - 228] = make_uint2(0u, 0u);

    __syncthreads();

    if (tid < 75) {
        float4 t = acc;
        const float4 p0 = s_part[0][tid], p1 = s_part[1][tid];
        t.x = (t.x + p0.x + p1.x) * (1.0f / 32.0f);
        t.y = (t.y + p0.y + p1.y) * (1.0f / 32.0f);
        t.z = (t.z + p0.z + p1.z) * (1.0f / 32.0f);
        t.w = (t.w + p0.w + p1.w) * (1.0f / 32.0f);
        ((uint2*)eb)[tid] = make_uint2(bf2_bits(t.x, t.y), bf2_bits(t.z, t.w));
    } else if (tid >= 80 && tid < 128) {
        const int f = (tid - 80) >> 4, c = (tid - 80) & 15;
        const float* tab = (f == 0) ? em1 : (f == 1) ? em2 : em3;
        const int* sidx = (f == 0) ? s_m1 : (f == 1) ? s_m2 : s_m3;
        float4 s = make_float4(0.f, 0.f, 0.f, 0.f);
        #pragma unroll
        for (int j = 0; j < L_MH; j++) {
            const float4 v = *(const float4*)(tab + (size_t)sidx[j] * EMB + c * 4);
            s.x += v.x; s.y += v.y; s.z += v.z; s.w += v.w;
        }
        __nv_bfloat16* dst = eb + 300 + f * 64 + c * 4;
        *(uint2*)dst = make_uint2(bf2_bits(s.x * 0.05f, s.y * 0.05f),
                                  bf2_bits(s.z * 0.05f, s.w * 0.05f));
    } else if (tid >= 128 && tid < 192) {
        const int f = (tid - 128) >> 4, c = (tid - 128) & 15;
        const float* tab = (f == 0) ? eo1 : (f == 1) ? eo2 : (f == 2) ? eo3 : eo4;
        const float4 v = *(const float4*)(tab + (size_t)s_oh[f] * EMB + c * 4);
        __nv_bfloat16* dst = eb + 492 + f * 64 + c * 4;
        *(uint2*)dst = make_uint2(bf2_bits(v.x, v.y), bf2_bits(v.z, v.w));
    } else if (tid >= 192 && tid < 224) {
        const int lane = tid - 192;
        float s = 0.f;
        if (lane < L_MH)
            s = wm1[s_m1[lane]] + wm2[s_m2[lane]] + wm3[s_m3[lane]];
        #pragma unroll
        for (int o = 16; o; o >>= 1) s += __shfl_xor_sync(0xFFFFFFFFu, s, o);
        if (lane == 0) {
            s += wo1[s_oh[0]] + wo2[s_oh[1]] + wo3[s_oh[2]] + wo4[s_oh[3]];
            g_wide[b] = s;
        }
    }
}

// ---------------------------------------------------------------------------
// Tensor-core GEMM: C = relu(A[M,K] @ Bt[N,K]^T + bias) -> bf16
// 128x128x64 CTA tile, 256 thr (2x4 warps, 64x32 warp tile), mma m16n8k16,
// 3-stage cp.async pipeline (96 KB dynamic smem), ldmatrix.x4, 8-chunk XOR
// swizzle (128 B rows).
// ---------------------------------------------------------------------------
__device__ __forceinline__ void mma16816(float c[4], const uint32_t a[4],
                                         const uint32_t b[2])
{
    asm volatile(
        "mma.sync.aligned.m16n8k16.row.col.f32.bf16.bf16.f32 "
        "{%0,%1,%2,%3}, {%4,%5,%6,%7}, {%8,%9}, {%0,%1,%2,%3};"
        : "+f"(c[0]), "+f"(c[1]), "+f"(c[2]), "+f"(c[3])
        : "r"(a[0]), "r"(a[1]), "r"(a[2]), "r"(a[3]), "r"(b[0]), "r"(b[1]));
}

#define STAGE_BYTES 32768           // A 16K + B 16K (128 rows x 128 B each)

__global__ __launch_bounds__(256, 2) void gemm_tc_kernel(
    const __nv_bfloat16* __restrict__ A, const __nv_bfloat16* __restrict__ Bt,
    const float* __restrict__ bias, __nv_bfloat16* __restrict__ C,
    int Nout, int K)
{
    extern __shared__ __align__(1024) char sm[];   // 3 * STAGE_BYTES

    const int tid  = threadIdx.x;
    const int lane = tid & 31, warp = tid >> 5;
    const int wm   = warp & 1;
    const int wn   = warp >> 1;
    const int gid  = lane >> 2;
    const int tig  = lane & 3;
    const int bm   = blockIdx.y * 128, bn = blockIdx.x * 128;

    // cp.async: 1024 16B chunks per 128x64 tile, 4 per thread (A and B each)
    int offS[4], gA[4], gB[4];
    #pragma unroll
    for (int j = 0; j < 4; j++) {
        const int c = tid + j * 256;
        const int r = c >> 3, ch = c & 7;
        offS[j] = r * 128 + ((ch ^ (r & 7)) << 4);
        gA[j]   = (bm + r) * K + ch * 8;
        gB[j]   = (bn + r) * K + ch * 8;
    }

    const int NIT = K >> 6;   // K / 64

    // ldmatrix per-lane addressing (128 B rows, 8-chunk XOR swizzle)
    const int q = lane >> 3, r8 = lane & 7;
    const int qa = q >> 1, qb = q & 1;
    uint32_t arow128[4]; int akey[4];
    #pragma unroll
    for (int mf = 0; mf < 4; mf++) {
        const int row = wm * 64 + mf * 16 + (q & 1) * 8 + r8;
        arow128[mf] = row * 128;
        akey[mf]    = row & 7;
    }
    uint32_t brow128[2]; int bkey[2];
    #pragma unroll
    for (int g = 0; g < 2; g++) {
        const int row = wn * 32 + g * 16 + (q >> 1) * 8 + r8;
        brow128[g] = row * 128;
        bkey[g]    = row & 7;
    }

    float acc[4][4][4];
    #pragma unroll
    for (int mf = 0; mf < 4; mf++)
        #pragma unroll
        for (int nf = 0; nf < 4; nf++)
            #pragma unroll
            for (int i = 0; i < 4; i++) acc[mf][nf][i] = 0.f;

    #define PREFETCH(stage, kofs)                                              \
        do {                                                                   \
            char* _s = sm + (stage) * STAGE_BYTES;                             \
            _Pragma("unroll")                                                  \
            for (int _j = 0; _j < 4; _j++) {                                   \
                uint32_t _da = smem_u32(_s + offS[_j]);                        \
                uint32_t _db = _da + 16384;                                    \
                asm volatile("cp.async.cg.shared.global [%0], [%1], 16;"       \
                             :: "r"(_da), "l"(A + gA[_j] + (kofs)) : "memory");\
                asm volatile("cp.async.cg.shared.global [%0], [%1], 16;"       \
                             :: "r"(_db), "l"(Bt + gB[_j] + (kofs)) : "memory");\
            }                                                                  \
        } while (0)

    PREFETCH(0, 0);
    asm volatile("cp.async.commit_group;" ::: "memory");
    PREFETCH(1, 64);
    asm volatile("cp.async.commit_group;" ::: "memory");

    for (int it = 0; it < NIT; it++) {
        asm volatile("cp.async.wait_group 1;" ::: "memory");
        __syncthreads();

        if (it + 2 < NIT) {
            const int st = it + 2;
            PREFETCH(st % 3, st * 64);
        }
        asm volatile("cp.async.commit_group;" ::: "memory");

        const uint32_t AsU = smem_u32(sm + (it % 3) * STAGE_BYTES);
        const uint32_t BsU = AsU + 16384;

        #pragma unroll
        for (int s = 0; s < 4; s++) {
            uint32_t af[4][4], bf[4][2];
            #pragma unroll
            for (int mf = 0; mf < 4; mf++) {
                const uint32_t addr =
                    AsU + arow128[mf] + ((((s << 1) + qa) ^ akey[mf]) << 4);
                asm volatile(
                    "ldmatrix.sync.aligned.m8n8.x4.shared.b16 {%0,%1,%2,%3}, [%4];"
                    : "=r"(af[mf][0]), "=r"(af[mf][1]),
                      "=r"(af[mf][2]), "=r"(af[mf][3])
                    : "r"(addr));
            }
            #pragma unroll
            for (int g = 0; g < 2; g++) {
                const uint32_t addr =
                    BsU + brow128[g] + ((((s << 1) + qb) ^ bkey[g]) << 4);
                asm volatile(
                    "ldmatrix.sync.aligned.m8n8.x4.shared.b16 {%0,%1,%2,%3}, [%4];"
                    : "=r"(bf[2 * g][0]), "=r"(bf[2 * g][1]),
                      "=r"(bf[2 * g + 1][0]), "=r"(bf[2 * g + 1][1])
                    : "r"(addr));
            }
            #pragma unroll
            for (int mf = 0; mf < 4; mf++)
                #pragma unroll
                for (int nf = 0; nf < 4; nf++)
                    mma16816(acc[mf][nf], af[mf], bf[nf]);
        }
    }
    #undef PREFETCH

    // epilogue: bias + ReLU -> bf16
    #pragma unroll
    for (int nf = 0; nf < 4; nf++) {
        const int col = bn + wn * 32 + nf * 8 + tig * 2;
        const float bv0 = bias[col], bv1 = bias[col + 1];
        #pragma unroll
        for (int mf = 0; mf < 4; mf++) {
            const int row0 = bm + wm * 64 + mf * 16 + gid;
            const float v00 = fmaxf(acc[mf][nf][0] + bv0, 0.f);
            const float v01 = fmaxf(acc[mf][nf][1] + bv1, 0.f);
            const float v10 = fmaxf(acc[mf][nf][2] + bv0, 0.f);
            const float v11 = fmaxf(acc[mf][nf][3] + bv1, 0.f);
            *(__nv_bfloat162*)(C + (size_t)row0 * Nout + col) =
                __floats2bfloat162_rn(v00, v01);
            *(__nv_bfloat162*)(C + (size_t)(row0 + 8) * Nout + col) =
                __floats2bfloat162_rn(v10, v11);
        }
    }
}

// ---------------------------------------------------------------------------
// Final: out = sigmoid(h3 @ Wd + bd + wide). One warp per row, vectorized.
// ---------------------------------------------------------------------------
__global__ __launch_bounds__(256) void final_kernel(
    const float* __restrict__ Wd, const float* __restrict__ bd,
    float* __restrict__ out)
{
    const int warp = threadIdx.x >> 5;
    const int lane = threadIdx.x & 31;
    const int b    = blockIdx.x * 8 + warp;

    const __nv_bfloat16* h = g_h3b + (size_t)b * N3;
    const uint4 hv = ((const uint4*)h)[lane];
    const float4 w0 = ((const float4*)Wd)[lane * 2];
    const float4 w1 = ((const float4*)Wd)[lane * 2 + 1];

    const __nv_bfloat162* hp = (const __nv_bfloat162*)&hv;
    float s = 0.f;
    float2 p;
    p = __bfloat1622float2(hp[0]); s += p.x * w0.x + p.y * w0.y;
    p = __bfloat1622float2(hp[1]); s += p.x * w0.z + p.y * w0.w;
    p = __bfloat1622float2(hp[2]); s += p.x * w1.x + p.y * w1.y;
    p = __bfloat1622float2(hp[3]); s += p.x * w1.z + p.y * w1.w;

    #pragma unroll
    for (int o = 16; o; o >>= 1) s += __shfl_xor_sync(0xFFFFFFFFu, s, o);

    if (lane == 0) {
        const float logit = s + bd[0] + g_wide[b];
        out[b] = 1.0f / (1.0f + expf(-logit));
    }
}

// ---------------------------------------------------------------------------
extern "C" void kernel_launch(void* const* d_in, const int* in_sizes, int n_in,
                              void* d_out, int out_size)
{
    (void)in_sizes; (void)n_in; (void)out_size;

    const int*   tok = (const int*)d_in[0];
    const int*   m1  = (const int*)d_in[1];
    const int*   m2  = (const int*)d_in[2];
    const int*   m3  = (const int*)d_in[3];
    const int*   o1  = (const int*)d_in[4];
    const int*   o2  = (const int*)d_in[5];
    const int*   o3  = (const int*)d_in[6];
    const int*   o4  = (const int*)d_in[7];
    const float* we  = (const float*)d_in[8];
    const float* em1 = (const float*)d_in[9];
    const float* em2 = (const float*)d_in[10];
    const float* em3 = (const float*)d_in[11];
    const float* eo1 = (const float*)d_in[12];
    const float* eo2 = (const float*)d_in[13];
    const float* eo3 = (const float*)d_in[14];
    const float* eo4 = (const float*)d_in[15];
    const float* wm1 = (const float*)d_in[16];
    const float* wm2 = (const float*)d_in[17];
    const float* wm3 = (const float*)d_in[18];
    const float* wo1 = (const float*)d_in[19];
    const float* wo2 = (const float*)d_in[20];
    const float* wo3 = (const float*)d_in[21];
    const float* wo4 = (const float*)d_in[22];
    const float* W1  = (const float*)d_in[23];
    const float* b1  = (const float*)d_in[24];
    const float* W2  = (const float*)d_in[25];
    const float* b2  = (const float*)d_in[26];
    const float* W3  = (const float*)d_in[27];
    const float* b3  = (const float*)d_in[28];
    const float* Wd  = (const float*)d_in[29];
    const float* bd  = (const float*)d_in[30];
    float* out = (float*)d_out;

    void *p_embB, *p_h1, *p_h2, *p_h3, *p_wt1, *p_wt2, *p_wt3;
    cudaGetSymbolAddress(&p_embB, g_embB);
    cudaGetSymbolAddress(&p_h1,   g_h1b);
    cudaGetSymbolAddress(&p_h2,   g_h2b);
    cudaGetSymbolAddress(&p_h3,   g_h3b);
    cudaGetSymbolAddress(&p_wt1,  g_Wt1);
    cudaGetSymbolAddress(&p_wt2,  g_Wt2);
    cudaGetSymbolAddress(&p_wt3,  g_Wt3);

    const int SMEM_DYN = 3 * STAGE_BYTES;   // 96 KB
    static int smem_set = 0;
    if (!smem_set) {
        cudaFuncSetAttribute(gemm_tc_kernel,
                             cudaFuncAttributeMaxDynamicSharedMemorySize, SMEM_DYN);
        smem_set = 1;
    }

    embed_prep_kernel<<<B_SZ + 768 + 512 + 128, 256>>>(
        tok, m1, m2, m3, o1, o2, o3, o4,
        we, em1, em2, em3, eo1, eo2, eo3, eo4,
        wm1, wm2, wm3, wo1, wo2, wo3, wo4,
        W1, W2, W3);

    gemm_tc_kernel<<<dim3(N1 / 128, B_SZ / 128), 256, SMEM_DYN>>>(
        (const __nv_bfloat16*)p_embB, (const __nv_bfloat16*)p_wt1, b1,
        (__nv_bfloat16*)p_h1, N1, K1P);
    gemm_tc_kernel<<<dim3(N2 / 128, B_SZ / 128), 256, SMEM_DYN>>>(
        (const __nv_bfloat16*)p_h1, (const __nv_bfloat16*)p_wt2, b2,
        (__nv_bfloat16*)p_h2, N2, N1);
    gemm_tc_kernel<<<dim3(N3 / 128, B_SZ / 128), 256, SMEM_DYN>>>(
        (const __nv_bfloat16*)p_h2, (const __nv_bfloat16*)p_wt3, b3,
        (__nv_bfloat16*)p_h3, N3, N2);

    final_kernel<<<B_SZ / 8, 256>>>(Wd, bd, out);
}